// round 1
// baseline (speedup 1.0000x reference)
#include <cuda_runtime.h>

// ---------------------------------------------------------------------------
// InstanceModelClassic: rigid-transform trilinear resampling of a 256^3 volume
//
// Inputs (metadata order):
//   d_in[0] image_targ  float32 [1,1,D,H,W]   (D=H=W=256 -> 16777216 elems)
//   d_in[1] rotation    float32 [1,3]
//   d_in[2] translation float32 [1,3]
//   d_in[3] ref_v2r     float32 [4,4]
//   d_in[4] flo_v2r     float32 [4,4]
// Output: float32 [1,1,D,H,W]
// ---------------------------------------------------------------------------

// 3 rows x 4 cols of the composed voxel->voxel transform
__device__ float g_T[12];

__device__ static void mat4_inv(const float* A, float* Ainv) {
    // Gauss-Jordan with partial pivoting on a 4x8 augmented matrix.
    float M[4][8];
    for (int r = 0; r < 4; r++) {
        for (int c = 0; c < 4; c++) {
            M[r][c] = A[r * 4 + c];
            M[r][4 + c] = (r == c) ? 1.0f : 0.0f;
        }
    }
    for (int col = 0; col < 4; col++) {
        // pivot
        int piv = col;
        float best = fabsf(M[col][col]);
        for (int r = col + 1; r < 4; r++) {
            float v = fabsf(M[r][col]);
            if (v > best) { best = v; piv = r; }
        }
        if (piv != col) {
            for (int c = 0; c < 8; c++) {
                float t = M[col][c]; M[col][c] = M[piv][c]; M[piv][c] = t;
            }
        }
        float inv_p = 1.0f / M[col][col];
        for (int c = 0; c < 8; c++) M[col][c] *= inv_p;
        for (int r = 0; r < 4; r++) {
            if (r == col) continue;
            float f = M[r][col];
            if (f != 0.0f) {
                for (int c = 0; c < 8; c++) M[r][c] -= f * M[col][c];
            }
        }
    }
    for (int r = 0; r < 4; r++)
        for (int c = 0; c < 4; c++)
            Ainv[r * 4 + c] = M[r][4 + c];
}

__device__ static void mm4(const float* A, const float* B, float* C) {
    for (int r = 0; r < 4; r++)
        for (int c = 0; c < 4; c++) {
            float s = 0.0f;
            for (int k = 0; k < 4; k++) s += A[r * 4 + k] * B[k * 4 + c];
            C[r * 4 + c] = s;
        }
}

__global__ void setup_transform_kernel(const float* __restrict__ rotation,
                                       const float* __restrict__ translation,
                                       const float* __restrict__ ref_v2r,
                                       const float* __restrict__ flo_v2r) {
    // Single thread: compose T = inv(flo_v2r) @ T_rig @ ref_v2r
    float cx = cosf(rotation[0]), cy = cosf(rotation[1]), cz = cosf(rotation[2]);
    float sx = sinf(rotation[0]), sy = sinf(rotation[1]), sz = sinf(rotation[2]);

    // R = Rx @ Ry @ Rz (3x3)
    float Rx[9] = {1, 0, 0,   0, cx, -sx,   0, sx, cx};
    float Ry[9] = {cy, 0, sy, 0, 1, 0,      -sy, 0, cy};
    float Rz[9] = {cz, -sz, 0, sz, cz, 0,   0, 0, 1};
    float Ryz[9], R[9];
    for (int r = 0; r < 3; r++)
        for (int c = 0; c < 3; c++) {
            float s = 0.0f;
            for (int k = 0; k < 3; k++) s += Ry[r * 3 + k] * Rz[k * 3 + c];
            Ryz[r * 3 + c] = s;
        }
    for (int r = 0; r < 3; r++)
        for (int c = 0; c < 3; c++) {
            float s = 0.0f;
            for (int k = 0; k < 3; k++) s += Rx[r * 3 + k] * Ryz[k * 3 + c];
            R[r * 3 + c] = s;
        }

    float Trig[16];
    for (int r = 0; r < 3; r++) {
        for (int c = 0; c < 3; c++) Trig[r * 4 + c] = R[r * 3 + c];
        Trig[r * 4 + 3] = translation[r];
    }
    Trig[12] = 0.0f; Trig[13] = 0.0f; Trig[14] = 0.0f; Trig[15] = 1.0f;

    float Finv[16], tmp[16], T[16];
    mat4_inv(flo_v2r, Finv);
    mm4(Trig, ref_v2r, tmp);
    mm4(Finv, tmp, T);

    for (int i = 0; i < 12; i++) g_T[i] = T[i];
}

template <int D, int H, int W>
__global__ void __launch_bounds__(256)
warp_trilinear_kernel(const float* __restrict__ img, float* __restrict__ out) {
    // Each thread produces 4 consecutive k voxels and writes one float4.
    const int idx = blockIdx.x * blockDim.x + threadIdx.x;
    const int KQ = W / 4;
    const int kq = (idx % KQ) * 4;
    const int j = (idx / KQ) % H;
    const int i = idx / (KQ * H);
    if (i >= D) return;

    const float T00 = g_T[0], T01 = g_T[1],  T02 = g_T[2],  T03 = g_T[3];
    const float T10 = g_T[4], T11 = g_T[5],  T12 = g_T[6],  T13 = g_T[7];
    const float T20 = g_T[8], T21 = g_T[9],  T22 = g_T[10], T23 = g_T[11];

    const float fi = (float)i, fj = (float)j, fk = (float)kq;
    float di = fmaf(T00, fi, fmaf(T01, fj, fmaf(T02, fk, T03)));
    float dj = fmaf(T10, fi, fmaf(T11, fj, fmaf(T12, fk, T13)));
    float dk = fmaf(T20, fi, fmaf(T21, fj, fmaf(T22, fk, T23)));

    const float dmax = (float)(D - 1);
    const float hmax = (float)(H - 1);
    const float wmax = (float)(W - 1);

    float4 res;
    float* resp = &res.x;

#pragma unroll
    for (int e = 0; e < 4; e++) {
        const float II = di + T02 * (float)e;
        const float JJ = dj + T12 * (float)e;
        const float KK = dk + T22 * (float)e;

        const bool ok = (II > 0.0f) && (JJ > 0.0f) && (KK > 0.0f) &&
                        (II <= dmax) && (JJ <= hmax) && (KK <= wmax);

        const float fx = floorf(II);
        const float fy = floorf(JJ);
        const float fz = floorf(KK);
        const float wcx = II - fx, wfx = 1.0f - wcx;
        const float wcy = JJ - fy, wfy = 1.0f - wcy;
        const float wcz = KK - fz, wfz = 1.0f - wcz;

        int x0 = min(max((int)fx, 0), D - 1);
        int y0 = min(max((int)fy, 0), H - 1);
        int z0 = min(max((int)fz, 0), W - 1);
        int x1 = min(x0 + 1, D - 1);
        int y1 = min(y0 + 1, H - 1);
        int z1 = min(z0 + 1, W - 1);

        float v = 0.0f;
        if (ok) {
            const int bx0 = x0 * (H * W);
            const int bx1 = x1 * (H * W);
            const int r00 = bx0 + y0 * W;
            const int r01 = bx0 + y1 * W;
            const int r10 = bx1 + y0 * W;
            const int r11 = bx1 + y1 * W;

            const float v000 = __ldg(img + r00 + z0);
            const float v001 = __ldg(img + r00 + z1);
            const float v010 = __ldg(img + r01 + z0);
            const float v011 = __ldg(img + r01 + z1);
            const float v100 = __ldg(img + r10 + z0);
            const float v101 = __ldg(img + r10 + z1);
            const float v110 = __ldg(img + r11 + z0);
            const float v111 = __ldg(img + r11 + z1);

            // Same summation structure as the reference (8 weighted terms)
            v = v000 * (wfx * wfy * wfz) +
                v001 * (wfx * wfy * wcz) +
                v010 * (wfx * wcy * wfz) +
                v011 * (wfx * wcy * wcz) +
                v100 * (wcx * wfy * wfz) +
                v101 * (wcx * wfy * wcz) +
                v110 * (wcx * wcy * wfz) +
                v111 * (wcx * wcy * wcz);
        }
        resp[e] = v;
    }

    const int out_idx = (i * H + j) * W + kq;
    *reinterpret_cast<float4*>(out + out_idx) = res;
}

extern "C" void kernel_launch(void* const* d_in, const int* in_sizes, int n_in,
                              void* d_out, int out_size) {
    const float* img         = (const float*)d_in[0];
    const float* rotation    = (const float*)d_in[1];
    const float* translation = (const float*)d_in[2];
    const float* ref_v2r     = (const float*)d_in[3];
    const float* flo_v2r     = (const float*)d_in[4];
    float* out = (float*)d_out;

    setup_transform_kernel<<<1, 1>>>(rotation, translation, ref_v2r, flo_v2r);

    constexpr int D = 256, H = 256, W = 256;
    const int total_threads = D * H * (W / 4);
    const int block = 256;
    const int grid = (total_threads + block - 1) / block;
    warp_trilinear_kernel<D, H, W><<<grid, block>>>(img, out);
}

// round 2
// speedup vs baseline: 1.7087x; 1.7087x over previous
#include <cuda_runtime.h>

// ---------------------------------------------------------------------------
// InstanceModelClassic: rigid-transform trilinear resampling of a 256^3 volume
//
// Inputs (metadata order):
//   d_in[0] image_targ  float32 [1,1,256,256,256]
//   d_in[1] rotation    float32 [1,3]
//   d_in[2] translation float32 [1,3]
//   d_in[3] ref_v2r     float32 [4,4]
//   d_in[4] flo_v2r     float32 [4,4]
// Output: float32 [1,1,256,256,256]
// ---------------------------------------------------------------------------

// 3 rows x 4 cols of the composed voxel->voxel transform
__device__ float g_T[12];

__device__ static void mat4_inv(const float* A, float* Ainv) {
    float M[4][8];
    for (int r = 0; r < 4; r++) {
        for (int c = 0; c < 4; c++) {
            M[r][c] = A[r * 4 + c];
            M[r][4 + c] = (r == c) ? 1.0f : 0.0f;
        }
    }
    for (int col = 0; col < 4; col++) {
        int piv = col;
        float best = fabsf(M[col][col]);
        for (int r = col + 1; r < 4; r++) {
            float v = fabsf(M[r][col]);
            if (v > best) { best = v; piv = r; }
        }
        if (piv != col) {
            for (int c = 0; c < 8; c++) {
                float t = M[col][c]; M[col][c] = M[piv][c]; M[piv][c] = t;
            }
        }
        float inv_p = 1.0f / M[col][col];
        for (int c = 0; c < 8; c++) M[col][c] *= inv_p;
        for (int r = 0; r < 4; r++) {
            if (r == col) continue;
            float f = M[r][col];
            if (f != 0.0f)
                for (int c = 0; c < 8; c++) M[r][c] -= f * M[col][c];
        }
    }
    for (int r = 0; r < 4; r++)
        for (int c = 0; c < 4; c++)
            Ainv[r * 4 + c] = M[r][4 + c];
}

__device__ static void mm4(const float* A, const float* B, float* C) {
    for (int r = 0; r < 4; r++)
        for (int c = 0; c < 4; c++) {
            float s = 0.0f;
            for (int k = 0; k < 4; k++) s += A[r * 4 + k] * B[k * 4 + c];
            C[r * 4 + c] = s;
        }
}

__global__ void setup_transform_kernel(const float* __restrict__ rotation,
                                       const float* __restrict__ translation,
                                       const float* __restrict__ ref_v2r,
                                       const float* __restrict__ flo_v2r) {
    float cx = cosf(rotation[0]), cy = cosf(rotation[1]), cz = cosf(rotation[2]);
    float sx = sinf(rotation[0]), sy = sinf(rotation[1]), sz = sinf(rotation[2]);

    float Rx[9] = {1, 0, 0,   0, cx, -sx,   0, sx, cx};
    float Ry[9] = {cy, 0, sy, 0, 1, 0,      -sy, 0, cy};
    float Rz[9] = {cz, -sz, 0, sz, cz, 0,   0, 0, 1};
    float Ryz[9], R[9];
    for (int r = 0; r < 3; r++)
        for (int c = 0; c < 3; c++) {
            float s = 0.0f;
            for (int k = 0; k < 3; k++) s += Ry[r * 3 + k] * Rz[k * 3 + c];
            Ryz[r * 3 + c] = s;
        }
    for (int r = 0; r < 3; r++)
        for (int c = 0; c < 3; c++) {
            float s = 0.0f;
            for (int k = 0; k < 3; k++) s += Rx[r * 3 + k] * Ryz[k * 3 + c];
            R[r * 3 + c] = s;
        }

    float Trig[16];
    for (int r = 0; r < 3; r++) {
        for (int c = 0; c < 3; c++) Trig[r * 4 + c] = R[r * 3 + c];
        Trig[r * 4 + 3] = translation[r];
    }
    Trig[12] = 0.0f; Trig[13] = 0.0f; Trig[14] = 0.0f; Trig[15] = 1.0f;

    float Finv[16], tmp[16], T[16];
    mat4_inv(flo_v2r, Finv);
    mm4(Trig, ref_v2r, tmp);
    mm4(Finv, tmp, T);

    for (int i = 0; i < 12; i++) g_T[i] = T[i];
}

// lerp: a + t*(b-a)
__device__ __forceinline__ float lerpf(float a, float b, float t) {
    return fmaf(t, b - a, a);
}

__global__ void __launch_bounds__(256)
warp_trilinear_kernel(const float* __restrict__ img, float* __restrict__ out) {
    // Mapping: block = 256 threads = (64 k-lanes) x (4 j-rows).
    // Each thread handles 4 voxels at k = tx, tx+64, tx+128, tx+192.
    // Warp lanes are CONSECUTIVE in k -> every tap load is warp-contiguous.
    constexpr int D = 256, H = 256, W = 256;
    const int tx = threadIdx.x & 63;          // k base within row
    const int ty = threadIdx.x >> 6;          // j offset within block
    const int j = ((blockIdx.x & 63) << 2) + ty;
    const int i = blockIdx.x >> 6;

    const float T00 = g_T[0], T01 = g_T[1],  T02 = g_T[2],  T03 = g_T[3];
    const float T10 = g_T[4], T11 = g_T[5],  T12 = g_T[6],  T13 = g_T[7];
    const float T20 = g_T[8], T21 = g_T[9],  T22 = g_T[10], T23 = g_T[11];

    const float fi = (float)i, fj = (float)j;
    // per-thread base (k = 0 term)
    const float di0 = fmaf(T00, fi, fmaf(T01, fj, T03));
    const float dj0 = fmaf(T10, fi, fmaf(T11, fj, T13));
    const float dk0 = fmaf(T20, fi, fmaf(T21, fj, T23));

    const float dmax = 255.0f;

    float* orow = out + ((i * H + j) * W);

#pragma unroll
    for (int e = 0; e < 4; e++) {
        const int k = tx + (e << 6);
        const float fk = (float)k;
        const float II = fmaf(T02, fk, di0);
        const float JJ = fmaf(T12, fk, dj0);
        const float KK = fmaf(T22, fk, dk0);

        const bool ok = (II > 0.0f) & (JJ > 0.0f) & (KK > 0.0f) &
                        (II <= dmax) & (JJ <= dmax) & (KK <= dmax);

        float v = 0.0f;
        if (ok) {
            // ok guarantees 0 <= floor(.) <= 255
            const int x0 = __float2int_rd(II);
            const int y0 = __float2int_rd(JJ);
            const int z0 = __float2int_rd(KK);
            const float wx = II - (float)x0;
            const float wy = JJ - (float)y0;
            const float wz = KK - (float)z0;

            // clamped +1 offsets (avoid OOB read when coord == 255 exactly;
            // the corresponding weight is 0 there, matching the reference clip)
            const int ox = (x0 < D - 1) ? (H * W) : 0;
            const int oy = (y0 < H - 1) ? W : 0;
            const int oz = (z0 < W - 1) ? 1 : 0;

            const int base = (x0 << 16) | (y0 << 8) | z0;
            const float* p00 = img + base;            // x0,y0
            const float* p01 = p00 + oy;              // x0,y1
            const float* p10 = p00 + ox;              // x1,y0
            const float* p11 = p10 + oy;              // x1,y1

            const float v000 = __ldg(p00);
            const float v001 = __ldg(p00 + oz);
            const float v010 = __ldg(p01);
            const float v011 = __ldg(p01 + oz);
            const float v100 = __ldg(p10);
            const float v101 = __ldg(p10 + oz);
            const float v110 = __ldg(p11);
            const float v111 = __ldg(p11 + oz);

            const float c00 = lerpf(v000, v001, wz);
            const float c01 = lerpf(v010, v011, wz);
            const float c10 = lerpf(v100, v101, wz);
            const float c11 = lerpf(v110, v111, wz);
            const float c0  = lerpf(c00, c01, wy);
            const float c1  = lerpf(c10, c11, wy);
            v = lerpf(c0, c1, wx);
        }
        orow[k] = v;
    }
}

extern "C" void kernel_launch(void* const* d_in, const int* in_sizes, int n_in,
                              void* d_out, int out_size) {
    const float* img         = (const float*)d_in[0];
    const float* rotation    = (const float*)d_in[1];
    const float* translation = (const float*)d_in[2];
    const float* ref_v2r     = (const float*)d_in[3];
    const float* flo_v2r     = (const float*)d_in[4];
    float* out = (float*)d_out;

    setup_transform_kernel<<<1, 1>>>(rotation, translation, ref_v2r, flo_v2r);

    // grid: blockIdx.x = (i << 6) | (j >> 2); 256*64 = 16384 blocks
    warp_trilinear_kernel<<<16384, 256>>>(img, out);
}